// round 12
// baseline (speedup 1.0000x reference)
#include <cuda_runtime.h>

#define TT 4096
#define EE 64
#define HH 4096
#define TKK 8
#define NG  64            // GEMM-role blocks (they join fill when done)
#define NB  148           // total blocks = one per SM
#define CHUNK 4096        // float4s per warp fill chunk (64KB)

// ---- scratch (device globals; no allocations allowed) ----
__device__ int   g_id[TT * TKK];    // top-8 expert ids per token
__device__ float g_pr[TT * TKK];    // router prob for each selected expert
__device__ int   g_pos[TT * TKK];   // dispatch position within capacity
__device__ int   g_chunk;           // fill-chunk dispenser (reset by kC)
__device__ int   g_gemm_done;       // finished GEMM blocks   (reset by kC)

// ---- warp-level fill: grab 64KB chunks until exhausted ----
__device__ __forceinline__ void fill_warp(float4* __restrict__ o4, long long n4)
{
    const int lane = threadIdx.x & 31;
    const float4 z = make_float4(0.f, 0.f, 0.f, 0.f);
    for (;;) {
        int c = 0;
        if (lane == 0) c = atomicAdd(&g_chunk, 1);
        c = __shfl_sync(0xffffffffu, c, 0);
        long long base = (long long)c * CHUNK;
        if (base >= n4) return;
        if (base + CHUNK <= n4) {
            #pragma unroll 4
            for (int j = 0; j < CHUNK / 32; j++)
                __stcs(o4 + base + lane + j * 32, z);
        } else {
            for (long long i = base + lane; i < n4; i += 32)
                __stcs(o4 + i, z);
        }
    }
}

// ============================================================================
// mainA: 148 blocks x 256 thr.
//   bid <  NG : GEMM 64tok x 64exp tile (K-split2, 8tok x 4exp register tile,
//               f32x2 FMA) + softmax + top-8. The LAST GEMM block to finish
//               additionally computes all dispatch positions (hidden under
//               the ongoing fill on the other 147 SMs). Then joins the fill.
//   bid >= NG : zero-fill role from the start (warp chunk dispenser).
// ============================================================================
__global__ void __launch_bounds__(256, 1) mainA(const float* __restrict__ x,
                                                const float* __restrict__ w,
                                                float* __restrict__ out,
                                                long long outn)
{
    const int bid = blockIdx.x, tid = threadIdx.x;
    long long n4 = outn >> 2;

    if (bid >= NG) {                      // ---------------- fill role
        fill_warp((float4*)out, n4);
        return;
    }

    // ---------------- GEMM role ----------------
    __shared__ __align__(16) float Xs[64 * 66];   // [token][k] stride 66
    __shared__ __align__(16) float Ws[64 * 66];   // [expert][k] stride 66
    __shared__ int s_flag;
    float* P = Xs;                                // logits overlay

    const int t0   = bid * 64;
    const int half = tid >> 7;        // K-split half
    const int ht   = tid & 127;
    const int tx   = ht & 15;         // experts tx*4 .. tx*4+3
    const int ty   = ht >> 4;         // tokens  ty*8 .. ty*8+7

    unsigned long long A[16];
    #pragma unroll
    for (int i = 0; i < 16; i++) A[i] = 0ull;

    for (int h0 = 0; h0 < HH / 2; h0 += 32) {
        #pragma unroll
        for (int rr = 0; rr < 16; rr++) {
            int i = rr * 256 + tid;
            int t = i >> 6, r = i & 63;
            int gk = h0 + ((r >> 5) << 11) + (r & 31);
            Xs[t * 66 + r] = x[(long long)(t0 + t) * HH + gk];
            Ws[t * 66 + r] = w[(long long)t * HH + gk];
        }
        __syncthreads();

        unsigned long long c[16];
        #pragma unroll
        for (int i = 0; i < 16; i++) c[i] = 0ull;

        const float* xb = &Xs[(ty * 8) * 66 + half * 32];
        const float* wb = &Ws[(tx * 4) * 66 + half * 32];

        #pragma unroll 4
        for (int kk2 = 0; kk2 < 16; kk2++) {
            float2 xt[8], wt[4];
            #pragma unroll
            for (int j = 0; j < 8; j++) xt[j] = *(const float2*)&xb[j * 66 + kk2 * 2];
            #pragma unroll
            for (int j = 0; j < 4; j++) wt[j] = *(const float2*)&wb[j * 66 + kk2 * 2];

            #pragma unroll
            for (int s = 0; s < 2; s++) {
                float w0 = s ? wt[0].y : wt[0].x;
                float w1 = s ? wt[1].y : wt[1].x;
                float w2 = s ? wt[2].y : wt[2].x;
                float w3 = s ? wt[3].y : wt[3].x;
                unsigned long long wp0, wp1;
                asm("mov.b64 %0, {%1, %2};" : "=l"(wp0)
                    : "r"(__float_as_uint(w0)), "r"(__float_as_uint(w1)));
                asm("mov.b64 %0, {%1, %2};" : "=l"(wp1)
                    : "r"(__float_as_uint(w2)), "r"(__float_as_uint(w3)));
                #pragma unroll
                for (int j = 0; j < 8; j++) {
                    float xv = s ? xt[j].y : xt[j].x;
                    unsigned long long xx;
                    asm("mov.b64 %0, {%1, %1};" : "=l"(xx) : "r"(__float_as_uint(xv)));
                    asm("fma.rn.f32x2 %0, %1, %2, %0;" : "+l"(c[j * 2])     : "l"(wp0), "l"(xx));
                    asm("fma.rn.f32x2 %0, %1, %2, %0;" : "+l"(c[j * 2 + 1]) : "l"(wp1), "l"(xx));
                }
            }
        }
        #pragma unroll
        for (int i = 0; i < 16; i++)
            asm("add.rn.f32x2 %0, %1, %0;" : "+l"(A[i]) : "l"(c[i]));
        __syncthreads();
    }

    // ---- combine K-halves into logits P[t*66+e] ----
    if (half == 1) {
        #pragma unroll
        for (int j = 0; j < 8; j++)
            #pragma unroll
            for (int p = 0; p < 2; p++) {
                unsigned lo, hi;
                asm("mov.b64 {%0, %1}, %2;" : "=r"(lo), "=r"(hi) : "l"(A[j * 2 + p]));
                P[(ty * 8 + j) * 66 + tx * 4 + 2 * p]     = __uint_as_float(lo);
                P[(ty * 8 + j) * 66 + tx * 4 + 2 * p + 1] = __uint_as_float(hi);
            }
    }
    __syncthreads();
    if (half == 0) {
        #pragma unroll
        for (int j = 0; j < 8; j++)
            #pragma unroll
            for (int p = 0; p < 2; p++) {
                unsigned lo, hi;
                asm("mov.b64 {%0, %1}, %2;" : "=r"(lo), "=r"(hi) : "l"(A[j * 2 + p]));
                int b = (ty * 8 + j) * 66 + tx * 4 + 2 * p;
                P[b]     += __uint_as_float(lo);
                P[b + 1] += __uint_as_float(hi);
            }
    }
    __syncthreads();

    // ---- softmax + iterative top-8 (8 warps x 8 tokens) ----
    const int wrp = tid >> 5, lane = tid & 31;
    for (int tt = 0; tt < 8; tt++) {
        int t = wrp * 8 + tt;
        float v0 = P[t * 66 + lane], v1 = P[t * 66 + lane + 32];

        float m = fmaxf(v0, v1);
        #pragma unroll
        for (int o = 16; o; o >>= 1) m = fmaxf(m, __shfl_xor_sync(0xffffffffu, m, o));

        float z = __expf(v0 - m) + __expf(v1 - m);
        #pragma unroll
        for (int o = 16; o; o >>= 1) z += __shfl_xor_sync(0xffffffffu, z, o);

        float s0 = v0, s1 = v1;
        int   wid_[TKK];
        float wex[TKK];
        float ssum = 0.f;

        #pragma unroll
        for (int k = 0; k < TKK; k++) {
            unsigned b0 = __float_as_uint(s0);
            b0 ^= (b0 & 0x80000000u) ? 0xFFFFFFFFu : 0x80000000u;
            unsigned b1 = __float_as_uint(s1);
            b1 ^= (b1 & 0x80000000u) ? 0xFFFFFFFFu : 0x80000000u;
            unsigned long long k0 = ((unsigned long long)b0 << 6) | (unsigned)(63 - lane);
            unsigned long long k1 = ((unsigned long long)b1 << 6) | (unsigned)(63 - (lane + 32));
            unsigned long long kb = (k0 > k1) ? k0 : k1;
            #pragma unroll
            for (int o = 16; o; o >>= 1) {
                unsigned long long ok = __shfl_xor_sync(0xffffffffu, kb, o);
                if (ok > kb) kb = ok;
            }
            int widx = 63 - (int)(kb & 63);
            float wv = P[t * 66 + widx];
            wid_[k] = widx;
            float ew = __expf(wv - m);
            wex[k] = ew;
            ssum += ew;
            if (widx < 32) { if (lane == widx)      s0 = __int_as_float(0xff800000); }
            else           { if (lane == widx - 32) s1 = __int_as_float(0xff800000); }
        }

        float gs    = ssum / z;
        float denom = fmaxf(gs, 1.1920929e-07f);
        if (lane == 0) {
            int tok = t0 + t;
            #pragma unroll
            for (int k = 0; k < TKK; k++) {
                g_id[tok * TKK + k] = wid_[k];
                g_pr[tok * TKK + k] = wex[k] / (z * denom);
            }
        }
    }

    // ---- detect last GEMM block; it computes dispatch positions ----
    __syncthreads();
    __threadfence();
    if (tid == 0) s_flag = (atomicAdd(&g_gemm_done, 1) == NG - 1);
    __syncthreads();

    if (s_flag) {
        // ===== rank/position computation (hidden under fill, ~10us) =====
        __threadfence();                      // acquire other blocks' g_id
        int* cnt = (int*)Xs;                  // [8][64] counts
        int* sb  = cnt + TKK * EE;            // [8][64] bases
        int* rc  = sb + TKK * EE;             // [8][64] running counts

        for (int i = tid; i < TKK * EE; i += 256) cnt[i] = 0;
        __syncthreads();
        for (int i = tid; i < TT * TKK; i += 256)
            atomicAdd(&cnt[(i & 7) * EE + g_id[i]], 1);
        __syncthreads();

        {   // warp wrp handles k = wrp
            int k = wrp;
            for (int e = lane; e < EE; e += 32) {
                int b = 0;
                for (int kp = 0; kp < k; kp++) b += cnt[kp * EE + e];
                sb[k * EE + e] = b;
                rc[k * EE + e] = 0;
            }
            __syncwarp();
            for (int t0r = 0; t0r < TT; t0r += 32) {
                int t = t0r + lane;
                int e = g_id[t * TKK + k];
                unsigned peers = __match_any_sync(0xffffffffu, e);
                int before = __popc(peers & ((1u << lane) - 1));
                int rb = rc[k * EE + e];
                __syncwarp();
                if (before == 0) rc[k * EE + e] = rb + __popc(peers);
                g_pos[t * TKK + k] = sb[k * EE + e] + rb + before;
                __syncwarp();
            }
        }
        __syncthreads();
    }

    // ---- join the fill ----
    fill_warp((float4*)out, n4);
}

// ============================================================================
// kC: scatter 32768 nonzeros into the zeroed output; reset counters.
//   out = [combine_weights (T*E*C fp32) ; dispatch_mask as fp32 (T*E*C)]
//   Kernel boundary orders this after ALL of mainA (fill + g_pos writes).
// ============================================================================
__global__ void __launch_bounds__(256) kC(float* __restrict__ out, int C)
{
    if (blockIdx.x == 0 && threadIdx.x == 0) {
        g_chunk = 0;
        g_gemm_done = 0;
    }
    int i = blockIdx.x * 256 + threadIdx.x;
    if (i >= TT * TKK) return;
    int t = i >> 3;
    int e = g_id[i];
    int p = g_pos[i];
    if (p < C) {
        long long idx = ((long long)t * EE + e) * C + p;
        out[idx] = g_pr[i];
        out[(long long)TT * EE * C + idx] = 1.0f;
    }
}

extern "C" void kernel_launch(void* const* d_in, const int* in_sizes, int n_in,
                              void* d_out, int out_size)
{
    const float* x = (const float*)d_in[0];   // hidden_states [1,4096,4096]
    const float* w = (const float*)d_in[1];   // wg_weight [64,4096]
    float* out = (float*)d_out;

    long long outn = (long long)out_size;
    int C = (int)(outn / (2LL * TT * EE));    // capacity from buffer size

    mainA<<<NB, 256>>>(x, w, out, outn);      // fill || GEMM+top8+ranks
    kC<<<(TT * TKK + 255) / 256, 256>>>(out, C);  // scatter + reset
}

// round 13
// speedup vs baseline: 1.0796x; 1.0796x over previous
#include <cuda_runtime.h>

#define TT 4096
#define EE 64
#define HH 4096
#define TKK 8
#define NG  64            // GEMM-role blocks (they join fill when done)
#define NB  148           // total blocks = one per SM
#define CHUNK 4096        // float4s per warp fill chunk (64KB)

// ---- scratch (device globals; no allocations allowed) ----
__device__ int   g_id[TT * TKK];        // packed: expert | (local_rank<<8)
__device__ float g_pr[TT * TKK];        // router prob for each selected expert
__device__ int   g_hist[TKK * EE * NG]; // [k][e][b] per-block counts
__device__ int   g_chunk;               // fill-chunk dispenser (reset by kB3)

// ---- warp-level fill: grab 64KB chunks until exhausted ----
__device__ __forceinline__ void fill_warp(float4* __restrict__ o4, long long n4)
{
    const int lane = threadIdx.x & 31;
    const float4 z = make_float4(0.f, 0.f, 0.f, 0.f);
    for (;;) {
        int c = 0;
        if (lane == 0) c = atomicAdd(&g_chunk, 1);
        c = __shfl_sync(0xffffffffu, c, 0);
        long long base = (long long)c * CHUNK;
        if (base >= n4) return;
        if (base + CHUNK <= n4) {
            #pragma unroll 4
            for (int j = 0; j < CHUNK / 32; j++)
                __stcs(o4 + base + lane + j * 32, z);
        } else {
            for (long long i = base + lane; i < n4; i += 32)
                __stcs(o4 + i, z);
        }
    }
}

// ============================================================================
// mainA: 148 blocks x 256 thr.
//   bid <  NG : GEMM 64tok x 64exp tile + softmax + top-8, then a LOCAL
//               (all-smem) rank/hist epilogue (~2us), then joins the fill.
//   bid >= NG : zero-fill role from the start (warp chunk dispenser).
// ============================================================================
__global__ void __launch_bounds__(256, 1) mainA(const float* __restrict__ x,
                                                const float* __restrict__ w,
                                                float* __restrict__ out,
                                                long long outn)
{
    const int bid = blockIdx.x, tid = threadIdx.x;
    long long n4 = outn >> 2;

    if (bid >= NG) {                      // ---------------- fill role
        fill_warp((float4*)out, n4);
        return;
    }

    // ---------------- GEMM role ----------------
    __shared__ __align__(16) float Xs[64 * 66];   // [token][k] stride 66
    __shared__ __align__(16) float Ws[64 * 66];   // [expert][k] stride 66
    __shared__ unsigned char sid8[64][TKK];       // block-local top-8 ids
    __shared__ int rc_s[TKK][EE];                 // per-(k,e) running counts
    float* P = Xs;                                // logits overlay

    const int t0   = bid * 64;
    const int half = tid >> 7;        // K-split half
    const int ht   = tid & 127;
    const int tx   = ht & 15;         // experts tx*4 .. tx*4+3
    const int ty   = ht >> 4;         // tokens  ty*8 .. ty*8+7

    unsigned long long A[16];
    #pragma unroll
    for (int i = 0; i < 16; i++) A[i] = 0ull;

    for (int h0 = 0; h0 < HH / 2; h0 += 32) {
        #pragma unroll
        for (int rr = 0; rr < 16; rr++) {
            int i = rr * 256 + tid;
            int t = i >> 6, r = i & 63;
            int gk = h0 + ((r >> 5) << 11) + (r & 31);
            Xs[t * 66 + r] = x[(long long)(t0 + t) * HH + gk];
            Ws[t * 66 + r] = w[(long long)t * HH + gk];
        }
        __syncthreads();

        unsigned long long c[16];
        #pragma unroll
        for (int i = 0; i < 16; i++) c[i] = 0ull;

        const float* xb = &Xs[(ty * 8) * 66 + half * 32];
        const float* wb = &Ws[(tx * 4) * 66 + half * 32];

        #pragma unroll 4
        for (int kk2 = 0; kk2 < 16; kk2++) {
            float2 xt[8], wt[4];
            #pragma unroll
            for (int j = 0; j < 8; j++) xt[j] = *(const float2*)&xb[j * 66 + kk2 * 2];
            #pragma unroll
            for (int j = 0; j < 4; j++) wt[j] = *(const float2*)&wb[j * 66 + kk2 * 2];

            #pragma unroll
            for (int s = 0; s < 2; s++) {
                float w0 = s ? wt[0].y : wt[0].x;
                float w1 = s ? wt[1].y : wt[1].x;
                float w2 = s ? wt[2].y : wt[2].x;
                float w3 = s ? wt[3].y : wt[3].x;
                unsigned long long wp0, wp1;
                asm("mov.b64 %0, {%1, %2};" : "=l"(wp0)
                    : "r"(__float_as_uint(w0)), "r"(__float_as_uint(w1)));
                asm("mov.b64 %0, {%1, %2};" : "=l"(wp1)
                    : "r"(__float_as_uint(w2)), "r"(__float_as_uint(w3)));
                #pragma unroll
                for (int j = 0; j < 8; j++) {
                    float xv = s ? xt[j].y : xt[j].x;
                    unsigned long long xx;
                    asm("mov.b64 %0, {%1, %1};" : "=l"(xx) : "r"(__float_as_uint(xv)));
                    asm("fma.rn.f32x2 %0, %1, %2, %0;" : "+l"(c[j * 2])     : "l"(wp0), "l"(xx));
                    asm("fma.rn.f32x2 %0, %1, %2, %0;" : "+l"(c[j * 2 + 1]) : "l"(wp1), "l"(xx));
                }
            }
        }
        #pragma unroll
        for (int i = 0; i < 16; i++)
            asm("add.rn.f32x2 %0, %1, %0;" : "+l"(A[i]) : "l"(c[i]));
        __syncthreads();
    }

    // ---- combine K-halves into logits P[t*66+e] ----
    if (half == 1) {
        #pragma unroll
        for (int j = 0; j < 8; j++)
            #pragma unroll
            for (int p = 0; p < 2; p++) {
                unsigned lo, hi;
                asm("mov.b64 {%0, %1}, %2;" : "=r"(lo), "=r"(hi) : "l"(A[j * 2 + p]));
                P[(ty * 8 + j) * 66 + tx * 4 + 2 * p]     = __uint_as_float(lo);
                P[(ty * 8 + j) * 66 + tx * 4 + 2 * p + 1] = __uint_as_float(hi);
            }
    }
    __syncthreads();
    if (half == 0) {
        #pragma unroll
        for (int j = 0; j < 8; j++)
            #pragma unroll
            for (int p = 0; p < 2; p++) {
                unsigned lo, hi;
                asm("mov.b64 {%0, %1}, %2;" : "=r"(lo), "=r"(hi) : "l"(A[j * 2 + p]));
                int b = (ty * 8 + j) * 66 + tx * 4 + 2 * p;
                P[b]     += __uint_as_float(lo);
                P[b + 1] += __uint_as_float(hi);
            }
    }
    __syncthreads();

    // ---- softmax + iterative top-8 (8 warps x 8 tokens) ----
    const int wrp = tid >> 5, lane = tid & 31;
    for (int tt = 0; tt < 8; tt++) {
        int t = wrp * 8 + tt;
        float v0 = P[t * 66 + lane], v1 = P[t * 66 + lane + 32];

        float m = fmaxf(v0, v1);
        #pragma unroll
        for (int o = 16; o; o >>= 1) m = fmaxf(m, __shfl_xor_sync(0xffffffffu, m, o));

        float z = __expf(v0 - m) + __expf(v1 - m);
        #pragma unroll
        for (int o = 16; o; o >>= 1) z += __shfl_xor_sync(0xffffffffu, z, o);

        float s0 = v0, s1 = v1;
        int   wid_[TKK];
        float wex[TKK];
        float ssum = 0.f;

        #pragma unroll
        for (int k = 0; k < TKK; k++) {
            unsigned b0 = __float_as_uint(s0);
            b0 ^= (b0 & 0x80000000u) ? 0xFFFFFFFFu : 0x80000000u;
            unsigned b1 = __float_as_uint(s1);
            b1 ^= (b1 & 0x80000000u) ? 0xFFFFFFFFu : 0x80000000u;
            unsigned long long k0 = ((unsigned long long)b0 << 6) | (unsigned)(63 - lane);
            unsigned long long k1 = ((unsigned long long)b1 << 6) | (unsigned)(63 - (lane + 32));
            unsigned long long kb = (k0 > k1) ? k0 : k1;
            #pragma unroll
            for (int o = 16; o; o >>= 1) {
                unsigned long long ok = __shfl_xor_sync(0xffffffffu, kb, o);
                if (ok > kb) kb = ok;
            }
            int widx = 63 - (int)(kb & 63);
            float wv = P[t * 66 + widx];
            wid_[k] = widx;
            float ew = __expf(wv - m);
            wex[k] = ew;
            ssum += ew;
            if (widx < 32) { if (lane == widx)      s0 = __int_as_float(0xff800000); }
            else           { if (lane == widx - 32) s1 = __int_as_float(0xff800000); }
        }

        float gs    = ssum / z;
        float denom = fmaxf(gs, 1.1920929e-07f);
        if (lane == 0) {
            int tok = t0 + t;
            #pragma unroll
            for (int k = 0; k < TKK; k++) {
                sid8[t][k] = (unsigned char)wid_[k];
                g_pr[tok * TKK + k] = wex[k] / (z * denom);
            }
        }
    }

    // ---- LOCAL rank + histogram epilogue (all-smem, ~2us) ----
    for (int i = tid; i < TKK * EE; i += 256) ((int*)rc_s)[i] = 0;
    __syncthreads();
    {
        int k = wrp;                          // warp k handles slot k
        #pragma unroll
        for (int r = 0; r < 2; r++) {
            int t = r * 32 + lane;            // block-local token, ascending
            int e = (int)sid8[t][k];
            unsigned peers = __match_any_sync(0xffffffffu, e);
            int before = __popc(peers & ((1u << lane) - 1));
            int rb = rc_s[k][e];
            __syncwarp();
            if (before == 0) rc_s[k][e] = rb + __popc(peers);
            g_id[(t0 + t) * TKK + k] = e | ((rb + before) << 8);
            __syncwarp();
        }
        // write block-local counts: g_hist[k][e][b]
        g_hist[(k * EE + lane) * NG + bid]        = rc_s[k][lane];
        g_hist[(k * EE + lane + 32) * NG + bid]   = rc_s[k][lane + 32];
    }

    // ---- join the fill (no sync needed; kernel boundary orders the rest) ----
    fill_warp((float4*)out, n4);
}

// ============================================================================
// kB3: 8 blocks (one per k) x 256 thr. Bases from g_hist (independent L2-hot
//   loads, no chains), then scatter this k's 4096 (weight, mask) entries.
//   position(t,k) = sum_{k'<k} tot[k'][e] + sum_{b'<b} h[b'][k][e] + lrank
// ============================================================================
__global__ void __launch_bounds__(256) kB3(float* __restrict__ out, int C)
{
    const int k = blockIdx.x, tid = threadIdx.x;
    const int e = tid & 63, q = tid >> 6;           // q: quarter of b-range

    __shared__ int part[4][EE];      // partial sums of k'<k over b-quarters
    __shared__ int cumk[EE];         // sum_{k'<k} tot[k'][e]
    __shared__ int csum[4][EE];      // own-k quarter sums
    __shared__ int base_s[EE][NG + 1];  // [e][b], padded (65) vs bank conflicts

    if (k == 0 && tid == 0) g_chunk = 0;            // reset for next replay

    // 1) cross-k totals for k' < k (this thread: its e, its 16 b's)
    int p0 = 0;
    for (int kp = 0; kp < k; kp++) {
        const int* hp = &g_hist[(kp * EE + e) * NG + q * 16];
        #pragma unroll
        for (int j = 0; j < 16; j++) p0 += hp[j];
    }
    part[q][e] = p0;
    __syncthreads();
    if (q == 0) cumk[e] = part[0][e] + part[1][e] + part[2][e] + part[3][e];
    __syncthreads();

    // 2) own-k prefix over blocks b
    int h[16], pre[16], s = 0;
    {
        const int* hp = &g_hist[(k * EE + e) * NG + q * 16];
        #pragma unroll
        for (int j = 0; j < 16; j++) h[j] = hp[j];
        #pragma unroll
        for (int j = 0; j < 16; j++) { pre[j] = s; s += h[j]; }
    }
    csum[q][e] = s;
    __syncthreads();
    {
        int off = cumk[e];
        for (int qq = 0; qq < q; qq++) off += csum[qq][e];
        #pragma unroll
        for (int j = 0; j < 16; j++) base_s[e][q * 16 + j] = off + pre[j];
    }
    __syncthreads();

    // 3) scatter this k's 4096 entries
    long long halfOff = (long long)TT * EE * C;
    for (int t = tid; t < TT; t += 256) {
        int v  = g_id[t * TKK + k];
        int e2 = v & 255;
        int lr = v >> 8;
        int p  = base_s[e2][t >> 6] + lr;
        if (p < C) {
            long long idx = ((long long)t * EE + e2) * C + p;
            out[idx]           = g_pr[t * TKK + k];
            out[halfOff + idx] = 1.0f;
        }
    }
}

extern "C" void kernel_launch(void* const* d_in, const int* in_sizes, int n_in,
                              void* d_out, int out_size)
{
    const float* x = (const float*)d_in[0];   // hidden_states [1,4096,4096]
    const float* w = (const float*)d_in[1];   // wg_weight [64,4096]
    float* out = (float*)d_out;

    long long outn = (long long)out_size;
    int C = (int)(outn / (2LL * TT * EE));    // capacity from buffer size

    mainA<<<NB, 256>>>(x, w, out, outn);      // fill || GEMM+top8+local ranks
    kB3<<<TKK, 256>>>(out, C);                // bases + scatter + reset
}

// round 16
// speedup vs baseline: 1.0941x; 1.0135x over previous
#include <cuda_runtime.h>

#define TT 4096
#define EE 64
#define HH 4096
#define TKK 8
#define NG  64            // GEMM-role blocks (they join fill when done)
#define NB  148           // total blocks = one per SM
#define CHUNK 4096        // float4s per warp fill chunk (64KB)
#define NSEG 8            // scatter segments per k

// ---- scratch (device globals; no allocations allowed) ----
__device__ int   g_id[TT * TKK];        // packed: expert | (local_rank<<8)
__device__ float g_pr[TT * TKK];        // router prob for each selected expert
__device__ int   g_hist[TKK * EE * NG]; // [k][e][b] per-block counts
__device__ int   g_chunk;               // fill-chunk dispenser (reset by kB3)

// ---- warp-level fill: grab 64KB chunks until exhausted ----
__device__ __forceinline__ void fill_warp(float4* __restrict__ o4, long long n4)
{
    const int lane = threadIdx.x & 31;
    const float4 z = make_float4(0.f, 0.f, 0.f, 0.f);
    for (;;) {
        int c = 0;
        if (lane == 0) c = atomicAdd(&g_chunk, 1);
        c = __shfl_sync(0xffffffffu, c, 0);
        long long base = (long long)c * CHUNK;
        if (base >= n4) return;
        if (base + CHUNK <= n4) {
            #pragma unroll 4
            for (int j = 0; j < CHUNK / 32; j++)
                __stcs(o4 + base + lane + j * 32, z);
        } else {
            for (long long i = base + lane; i < n4; i += 32)
                __stcs(o4 + i, z);
        }
    }
}

// ============================================================================
// mainA: 148 blocks x 256 thr.
//   bid <  NG : GEMM 64tok x 64exp tile + softmax + top-8, then a LOCAL
//               (all-smem) rank/hist epilogue (~2us), then joins the fill.
//   bid >= NG : zero-fill role from the start (warp chunk dispenser).
// ============================================================================
__global__ void __launch_bounds__(256, 1) mainA(const float* __restrict__ x,
                                                const float* __restrict__ w,
                                                float* __restrict__ out,
                                                long long outn)
{
    const int bid = blockIdx.x, tid = threadIdx.x;
    long long n4 = outn >> 2;

    if (bid >= NG) {                      // ---------------- fill role
        fill_warp((float4*)out, n4);
        return;
    }

    // ---------------- GEMM role ----------------
    __shared__ __align__(16) float Xs[64 * 66];   // [token][k] stride 66
    __shared__ __align__(16) float Ws[64 * 66];   // [expert][k] stride 66
    __shared__ unsigned char sid8[64][TKK];       // block-local top-8 ids
    __shared__ int rc_s[TKK][EE];                 // per-(k,e) running counts
    float* P = Xs;                                // logits overlay

    const int t0   = bid * 64;
    const int half = tid >> 7;        // K-split half
    const int ht   = tid & 127;
    const int tx   = ht & 15;         // experts tx*4 .. tx*4+3
    const int ty   = ht >> 4;         // tokens  ty*8 .. ty*8+7

    unsigned long long A[16];
    #pragma unroll
    for (int i = 0; i < 16; i++) A[i] = 0ull;

    for (int h0 = 0; h0 < HH / 2; h0 += 32) {
        #pragma unroll
        for (int rr = 0; rr < 16; rr++) {
            int i = rr * 256 + tid;
            int t = i >> 6, r = i & 63;
            int gk = h0 + ((r >> 5) << 11) + (r & 31);
            Xs[t * 66 + r] = x[(long long)(t0 + t) * HH + gk];
            Ws[t * 66 + r] = w[(long long)t * HH + gk];
        }
        __syncthreads();

        unsigned long long c[16];
        #pragma unroll
        for (int i = 0; i < 16; i++) c[i] = 0ull;

        const float* xb = &Xs[(ty * 8) * 66 + half * 32];
        const float* wb = &Ws[(tx * 4) * 66 + half * 32];

        #pragma unroll 4
        for (int kk2 = 0; kk2 < 16; kk2++) {
            float2 xt[8], wt[4];
            #pragma unroll
            for (int j = 0; j < 8; j++) xt[j] = *(const float2*)&xb[j * 66 + kk2 * 2];
            #pragma unroll
            for (int j = 0; j < 4; j++) wt[j] = *(const float2*)&wb[j * 66 + kk2 * 2];

            #pragma unroll
            for (int s = 0; s < 2; s++) {
                float w0 = s ? wt[0].y : wt[0].x;
                float w1 = s ? wt[1].y : wt[1].x;
                float w2 = s ? wt[2].y : wt[2].x;
                float w3 = s ? wt[3].y : wt[3].x;
                unsigned long long wp0, wp1;
                asm("mov.b64 %0, {%1, %2};" : "=l"(wp0)
                    : "r"(__float_as_uint(w0)), "r"(__float_as_uint(w1)));
                asm("mov.b64 %0, {%1, %2};" : "=l"(wp1)
                    : "r"(__float_as_uint(w2)), "r"(__float_as_uint(w3)));
                #pragma unroll
                for (int j = 0; j < 8; j++) {
                    float xv = s ? xt[j].y : xt[j].x;
                    unsigned long long xx;
                    asm("mov.b64 %0, {%1, %1};" : "=l"(xx) : "r"(__float_as_uint(xv)));
                    asm("fma.rn.f32x2 %0, %1, %2, %0;" : "+l"(c[j * 2])     : "l"(wp0), "l"(xx));
                    asm("fma.rn.f32x2 %0, %1, %2, %0;" : "+l"(c[j * 2 + 1]) : "l"(wp1), "l"(xx));
                }
            }
        }
        #pragma unroll
        for (int i = 0; i < 16; i++)
            asm("add.rn.f32x2 %0, %1, %0;" : "+l"(A[i]) : "l"(c[i]));
        __syncthreads();
    }

    // ---- combine K-halves into logits P[t*66+e] ----
    if (half == 1) {
        #pragma unroll
        for (int j = 0; j < 8; j++)
            #pragma unroll
            for (int p = 0; p < 2; p++) {
                unsigned lo, hi;
                asm("mov.b64 {%0, %1}, %2;" : "=r"(lo), "=r"(hi) : "l"(A[j * 2 + p]));
                P[(ty * 8 + j) * 66 + tx * 4 + 2 * p]     = __uint_as_float(lo);
                P[(ty * 8 + j) * 66 + tx * 4 + 2 * p + 1] = __uint_as_float(hi);
            }
    }
    __syncthreads();
    if (half == 0) {
        #pragma unroll
        for (int j = 0; j < 8; j++)
            #pragma unroll
            for (int p = 0; p < 2; p++) {
                unsigned lo, hi;
                asm("mov.b64 {%0, %1}, %2;" : "=r"(lo), "=r"(hi) : "l"(A[j * 2 + p]));
                int b = (ty * 8 + j) * 66 + tx * 4 + 2 * p;
                P[b]     += __uint_as_float(lo);
                P[b + 1] += __uint_as_float(hi);
            }
    }
    __syncthreads();

    // ---- softmax + iterative top-8 (8 warps x 8 tokens) ----
    const int wrp = tid >> 5, lane = tid & 31;
    for (int tt = 0; tt < 8; tt++) {
        int t = wrp * 8 + tt;
        float v0 = P[t * 66 + lane], v1 = P[t * 66 + lane + 32];

        float m = fmaxf(v0, v1);
        #pragma unroll
        for (int o = 16; o; o >>= 1) m = fmaxf(m, __shfl_xor_sync(0xffffffffu, m, o));

        float z = __expf(v0 - m) + __expf(v1 - m);
        #pragma unroll
        for (int o = 16; o; o >>= 1) z += __shfl_xor_sync(0xffffffffu, z, o);

        float s0 = v0, s1 = v1;
        int   wid_[TKK];
        float wex[TKK];
        float ssum = 0.f;

        #pragma unroll
        for (int k = 0; k < TKK; k++) {
            unsigned b0 = __float_as_uint(s0);
            b0 ^= (b0 & 0x80000000u) ? 0xFFFFFFFFu : 0x80000000u;
            unsigned b1 = __float_as_uint(s1);
            b1 ^= (b1 & 0x80000000u) ? 0xFFFFFFFFu : 0x80000000u;
            unsigned long long k0 = ((unsigned long long)b0 << 6) | (unsigned)(63 - lane);
            unsigned long long k1 = ((unsigned long long)b1 << 6) | (unsigned)(63 - (lane + 32));
            unsigned long long kb = (k0 > k1) ? k0 : k1;
            #pragma unroll
            for (int o = 16; o; o >>= 1) {
                unsigned long long ok = __shfl_xor_sync(0xffffffffu, kb, o);
                if (ok > kb) kb = ok;
            }
            int widx = 63 - (int)(kb & 63);
            float wv = P[t * 66 + widx];
            wid_[k] = widx;
            float ew = __expf(wv - m);
            wex[k] = ew;
            ssum += ew;
            if (widx < 32) { if (lane == widx)      s0 = __int_as_float(0xff800000); }
            else           { if (lane == widx - 32) s1 = __int_as_float(0xff800000); }
        }

        float gs    = ssum / z;
        float denom = fmaxf(gs, 1.1920929e-07f);
        if (lane == 0) {
            int tok = t0 + t;
            #pragma unroll
            for (int k = 0; k < TKK; k++) {
                sid8[t][k] = (unsigned char)wid_[k];
                g_pr[tok * TKK + k] = wex[k] / (z * denom);
            }
        }
    }

    // ---- LOCAL rank + histogram epilogue (all-smem, ~2us) ----
    for (int i = tid; i < TKK * EE; i += 256) ((int*)rc_s)[i] = 0;
    __syncthreads();
    {
        int k = wrp;                          // warp k handles slot k
        #pragma unroll
        for (int r = 0; r < 2; r++) {
            int t = r * 32 + lane;            // block-local token, ascending
            int e = (int)sid8[t][k];
            unsigned peers = __match_any_sync(0xffffffffu, e);
            int before = __popc(peers & ((1u << lane) - 1));
            int rb = rc_s[k][e];
            __syncwarp();
            if (before == 0) rc_s[k][e] = rb + __popc(peers);
            g_id[(t0 + t) * TKK + k] = e | ((rb + before) << 8);
            __syncwarp();
        }
        // write block-local counts: g_hist[k][e][b]
        g_hist[(k * EE + lane) * NG + bid]        = rc_s[k][lane];
        g_hist[(k * EE + lane + 32) * NG + bid]   = rc_s[k][lane + 32];
    }

    // ---- join the fill (kernel boundary orders the rest) ----
    fill_warp((float4*)out, n4);
}

// ============================================================================
// kB3: 64 blocks x 256 thr.  k = bid/NSEG, segment = bid%NSEG (512 tokens).
//   Each block (redundantly, L2-hot) builds the base table for its k from
//   g_hist, then scatters its 512-token segment of (weight, mask) entries.
//   position(t,k) = sum_{k'<k} tot[k'][e] + sum_{b'<b} h[b'][k][e] + lrank
// ============================================================================
__global__ void __launch_bounds__(256) kB3(float* __restrict__ out, int C)
{
    const int k   = blockIdx.x / NSEG;
    const int seg = blockIdx.x % NSEG;
    const int tid = threadIdx.x;
    const int e = tid & 63, q = tid >> 6;           // q: quarter of b-range

    __shared__ int part[4][EE];      // partial sums of k'<k over b-quarters
    __shared__ int cumk[EE];         // sum_{k'<k} tot[k'][e]
    __shared__ int csum[4][EE];      // own-k quarter sums
    __shared__ int base_s[EE][NG + 1];  // [e][b], padded vs bank conflicts

    if (blockIdx.x == 0 && tid == 0) g_chunk = 0;   // reset for next replay

    // 1) cross-k totals for k' < k (this thread: its e, its 16 b's)
    int p0 = 0;
    for (int kp = 0; kp < k; kp++) {
        const int* hp = &g_hist[(kp * EE + e) * NG + q * 16];
        #pragma unroll
        for (int j = 0; j < 16; j++) p0 += hp[j];
    }
    part[q][e] = p0;
    __syncthreads();
    if (q == 0) cumk[e] = part[0][e] + part[1][e] + part[2][e] + part[3][e];
    __syncthreads();

    // 2) own-k prefix over blocks b
    int h[16], pre[16], s = 0;
    {
        const int* hp = &g_hist[(k * EE + e) * NG + q * 16];
        #pragma unroll
        for (int j = 0; j < 16; j++) h[j] = hp[j];
        #pragma unroll
        for (int j = 0; j < 16; j++) { pre[j] = s; s += h[j]; }
    }
    csum[q][e] = s;
    __syncthreads();
    {
        int off = cumk[e];
        for (int qq = 0; qq < q; qq++) off += csum[qq][e];
        #pragma unroll
        for (int j = 0; j < 16; j++) base_s[e][q * 16 + j] = off + pre[j];
    }
    __syncthreads();

    // 3) scatter this segment's 512 entries for slot k
    long long halfOff = (long long)TT * EE * C;
    #pragma unroll
    for (int r = 0; r < 2; r++) {
        int t = seg * 512 + r * 256 + tid;
        int v  = g_id[t * TKK + k];
        int e2 = v & 255;
        int lr = v >> 8;
        int p  = base_s[e2][t >> 6] + lr;
        if (p < C) {
            long long idx = ((long long)t * EE + e2) * C + p;
            out[idx]           = g_pr[t * TKK + k];
            out[halfOff + idx] = 1.0f;
        }
    }
}

extern "C" void kernel_launch(void* const* d_in, const int* in_sizes, int n_in,
                              void* d_out, int out_size)
{
    const float* x = (const float*)d_in[0];   // hidden_states [1,4096,4096]
    const float* w = (const float*)d_in[1];   // wg_weight [64,4096]
    float* out = (float*)d_out;

    long long outn = (long long)out_size;
    int C = (int)(outn / (2LL * TT * EE));    // capacity from buffer size

    mainA<<<NB, 256>>>(x, w, out, outn);      // fill || GEMM+top8+local ranks
    kB3<<<TKK * NSEG, 256>>>(out, C);         // bases + scatter + reset
}